// round 16
// baseline (speedup 1.0000x reference)
#include <cuda_runtime.h>
#include <cuda_bf16.h>

#define BB 2
#define CC 256
#define HH 96
#define WW 192
#define GROUPS 4
#define KK 9
#define HWSZ (HH * WW)

// NHWC scratch for left/right features (37.7 MB each). Static __device__
// arrays are the allowed scratch mechanism (no cudaMalloc anywhere).
__device__ __align__(16) float g_leftT[BB * HWSZ * CC];
__device__ __align__(16) float g_rightT[BB * HWSZ * CC];

// ---------------------------------------------------------------------------
// NCHW -> NHWC transpose. Treat each batch as a (C=256) x (HW=18432) matrix
// and produce (HW) x (C). 32x32 smem tiles, 32x8 threads. HW%32==0, C%32==0.
// ---------------------------------------------------------------------------
__global__ void transpose_nchw_nhwc(const float* __restrict__ in,
                                    float* __restrict__ out) {
    __shared__ float tile[32][33];
    const int b   = blockIdx.z;
    const int hw0 = blockIdx.x * 32;
    const int c0  = blockIdx.y * 32;
    const int tx  = threadIdx.x;   // 0..31
    const int ty  = threadIdx.y;   // 0..7

    const float* inb = in  + (size_t)b * CC * HWSZ;
    float*      outb = out + (size_t)b * HWSZ * CC;

#pragma unroll
    for (int j = 0; j < 32; j += 8) {
        const int c  = c0 + ty + j;
        const int hw = hw0 + tx;
        tile[ty + j][tx] = inb[(size_t)c * HWSZ + hw];   // coalesced read
    }
    __syncthreads();
#pragma unroll
    for (int j = 0; j < 32; j += 8) {
        const int hw = hw0 + ty + j;
        const int c  = c0 + tx;
        outb[(size_t)hw * CC + c] = tile[tx][ty + j];    // coalesced write
    }
}

// ---------------------------------------------------------------------------
// Main correlation kernel. One warp per pixel (b,h,w). Lane l owns channels
// [8l, 8l+8) -> group g = l/8. Per candidate k: compute bilinear coords,
// load 4 corner vectors (2x float4 per lane, contiguous NHWC), dot with the
// cached left vector, weight-combine, reduce over the 8 lanes of each group.
// ---------------------------------------------------------------------------
__global__ __launch_bounds__(256) void corr_kernel(
    const float* __restrict__ flow,
    const float* __restrict__ extra,
    float* __restrict__ out) {

    const int warp = (blockIdx.x * blockDim.x + threadIdx.x) >> 5;
    const int lane = threadIdx.x & 31;
    if (warp >= BB * HWSZ) return;

    const int b  = warp / HWSZ;
    const int hw = warp - b * HWSZ;
    const int h  = hw / WW;
    const int w  = hw - h * WW;

    // Cache this pixel's left-feature vector slice in registers.
    const float* lp = g_leftT + (size_t)warp * CC + lane * 8;
    const float4 l0 = *(const float4*)(lp);
    const float4 l1 = *(const float4*)(lp + 4);

    const float fx = __ldg(flow + (size_t)(b * 2 + 0) * HWSZ + hw);
    const float fy = __ldg(flow + (size_t)(b * 2 + 1) * HWSZ + hw);
    const float cxb = (float)w + fx;
    const float cyb = (float)h + fy;

    const float* rbase = g_rightT + (size_t)b * HWSZ * CC;
    const int g = lane >> 3;

#pragma unroll 1
    for (int k = 0; k < KK; k++) {
        const float ex = __ldg(extra + (size_t)(b * 2 * KK + 2 * k + 0) * HWSZ + hw);
        const float ey = __ldg(extra + (size_t)(b * 2 * KK + 2 * k + 1) * HWSZ + hw);

        const float cx = cxb + (float)(k - 4) + ex;
        const float cy = cyb + ey;

        const float x0f = floorf(cx);
        const float y0f = floorf(cy);
        const int x0 = (int)x0f;
        const int y0 = (int)y0f;
        const float ax = cx - x0f;
        const float ay = cy - y0f;

        float w00 = (1.0f - ax) * (1.0f - ay);
        float w01 = ax * (1.0f - ay);
        float w10 = (1.0f - ax) * ay;
        float w11 = ax * ay;

        const int x1 = x0 + 1, y1 = y0 + 1;
        const bool vx0 = (x0 >= 0) && (x0 <= WW - 1);
        const bool vx1 = (x1 >= 0) && (x1 <= WW - 1);
        const bool vy0 = (y0 >= 0) && (y0 <= HH - 1);
        const bool vy1 = (y1 >= 0) && (y1 <= HH - 1);
        if (!(vx0 && vy0)) w00 = 0.0f;
        if (!(vx1 && vy0)) w01 = 0.0f;
        if (!(vx0 && vy1)) w10 = 0.0f;
        if (!(vx1 && vy1)) w11 = 0.0f;

        const int ix0 = min(max(x0, 0), WW - 1);
        const int ix1 = min(max(x1, 0), WW - 1);
        const int iy0 = min(max(y0, 0), HH - 1);
        const int iy1 = min(max(y1, 0), HH - 1);

        const float* p00 = rbase + (size_t)(iy0 * WW + ix0) * CC + lane * 8;
        const float* p01 = rbase + (size_t)(iy0 * WW + ix1) * CC + lane * 8;
        const float* p10 = rbase + (size_t)(iy1 * WW + ix0) * CC + lane * 8;
        const float* p11 = rbase + (size_t)(iy1 * WW + ix1) * CC + lane * 8;

        // Issue all 8 corner loads up-front for MLP.
        const float4 a0 = *(const float4*)(p00);
        const float4 a1 = *(const float4*)(p00 + 4);
        const float4 b0 = *(const float4*)(p01);
        const float4 b1 = *(const float4*)(p01 + 4);
        const float4 c0 = *(const float4*)(p10);
        const float4 c1 = *(const float4*)(p10 + 4);
        const float4 d0 = *(const float4*)(p11);
        const float4 d1 = *(const float4*)(p11 + 4);

        float d00 = a0.x * l0.x + a0.y * l0.y + a0.z * l0.z + a0.w * l0.w
                  + a1.x * l1.x + a1.y * l1.y + a1.z * l1.z + a1.w * l1.w;
        float d01 = b0.x * l0.x + b0.y * l0.y + b0.z * l0.z + b0.w * l0.w
                  + b1.x * l1.x + b1.y * l1.y + b1.z * l1.z + b1.w * l1.w;
        float d10 = c0.x * l0.x + c0.y * l0.y + c0.z * l0.z + c0.w * l0.w
                  + c1.x * l1.x + c1.y * l1.y + c1.z * l1.z + c1.w * l1.w;
        float d11 = d0.x * l0.x + d0.y * l0.y + d0.z * l0.z + d0.w * l0.w
                  + d1.x * l1.x + d1.y * l1.y + d1.z * l1.z + d1.w * l1.w;

        float s = w00 * d00 + w01 * d01 + w10 * d10 + w11 * d11;

        // Reduce over the 8 lanes of this group (channels of group g).
        s += __shfl_xor_sync(0xffffffffu, s, 1);
        s += __shfl_xor_sync(0xffffffffu, s, 2);
        s += __shfl_xor_sync(0xffffffffu, s, 4);

        if ((lane & 7) == 0) {
            // out[b, g*K + k, h, w]
            out[((size_t)(b * GROUPS + g) * KK + k) * HWSZ + hw] = s * (1.0f / 64.0f);
        }
    }
}

extern "C" void kernel_launch(void* const* d_in, const int* in_sizes, int n_in,
                              void* d_out, int out_size) {
    const float* left  = (const float*)d_in[0];
    const float* right = (const float*)d_in[1];
    const float* flow  = (const float*)d_in[2];
    const float* extra = (const float*)d_in[3];
    float* out = (float*)d_out;

    float* leftT;
    float* rightT;
    cudaGetSymbolAddress((void**)&leftT, g_leftT);
    cudaGetSymbolAddress((void**)&rightT, g_rightT);

    // Prepass: NCHW -> NHWC for both feature maps.
    dim3 tgrid(HWSZ / 32, CC / 32, BB);   // (576, 8, 2)
    dim3 tblk(32, 8, 1);
    transpose_nchw_nhwc<<<tgrid, tblk>>>(left, leftT);
    transpose_nchw_nhwc<<<tgrid, tblk>>>(right, rightT);

    // Main kernel: one warp per pixel; 8 warps (8 consecutive w) per block.
    const int total_warps = BB * HWSZ;          // 36864
    const int threads = 256;                    // 8 warps
    const int blocks = (total_warps * 32 + threads - 1) / threads;  // 4608
    corr_kernel<<<blocks, threads>>>(flow, extra, out);
}

// round 17
// speedup vs baseline: 1.6718x; 1.6718x over previous
#include <cuda_runtime.h>
#include <cuda_fp16.h>
#include <cuda_bf16.h>

#define BB 2
#define CC 256
#define HH 96
#define WW 192
#define GROUPS 4
#define KK 9
#define HWSZ (HH * WW)

// NHWC fp16 scratch for right feature (18.9 MB). Static __device__ array is
// the allowed scratch mechanism (no cudaMalloc anywhere).
__device__ __align__(16) __half g_rightT[BB * HWSZ * CC];

// ---------------------------------------------------------------------------
// NCHW fp32 -> NHWC fp16 transpose+convert for the right feature.
// (C=256) x (HW=18432) -> (HW) x (C). 32x32 smem tiles, 32x8 threads.
// ---------------------------------------------------------------------------
__global__ void transpose_convert_f16(const float* __restrict__ in,
                                      __half* __restrict__ out) {
    __shared__ float tile[32][33];
    const int b   = blockIdx.z;
    const int hw0 = blockIdx.x * 32;
    const int c0  = blockIdx.y * 32;
    const int tx  = threadIdx.x;   // 0..31
    const int ty  = threadIdx.y;   // 0..7

    const float* inb = in  + (size_t)b * CC * HWSZ;
    __half*     outb = out + (size_t)b * HWSZ * CC;

#pragma unroll
    for (int j = 0; j < 32; j += 8) {
        const int c  = c0 + ty + j;
        const int hw = hw0 + tx;
        tile[ty + j][tx] = inb[(size_t)c * HWSZ + hw];   // coalesced read
    }
    __syncthreads();
#pragma unroll
    for (int j = 0; j < 32; j += 8) {
        const int hw = hw0 + ty + j;
        const int c  = c0 + tx;
        outb[(size_t)hw * CC + c] = __float2half_rn(tile[tx][ty + j]);
    }
}

// 8-halves (uint4) dot against 8 cached fp32 left values, fp32 accumulate.
__device__ __forceinline__ float dot8h(uint4 v, const float* l) {
    float2 f0 = __half22float2(*(__half2*)&v.x);
    float2 f1 = __half22float2(*(__half2*)&v.y);
    float2 f2 = __half22float2(*(__half2*)&v.z);
    float2 f3 = __half22float2(*(__half2*)&v.w);
    float s = f0.x * l[0];
    s = fmaf(f0.y, l[1], s);
    s = fmaf(f1.x, l[2], s);
    s = fmaf(f1.y, l[3], s);
    s = fmaf(f2.x, l[4], s);
    s = fmaf(f2.y, l[5], s);
    s = fmaf(f3.x, l[6], s);
    s = fmaf(f3.y, l[7], s);
    return s;
}

// ---------------------------------------------------------------------------
// Main correlation kernel. One warp per pixel; block = 8 consecutive-w pixels.
// Left feature is staged per-block from NCHW into smem (coalesced 32B sectors),
// so no left transpose prepass is needed. Right corners come from the fp16
// NHWC scratch: one LDG.128 per corner per lane (8 channels).
// ---------------------------------------------------------------------------
__global__ __launch_bounds__(256) void corr_kernel(
    const float* __restrict__ left,
    const float* __restrict__ flow,
    const float* __restrict__ extra,
    float* __restrict__ out) {

    __shared__ float s_left[8][260];   // +4 pad: conflict-light, keeps 16B align

    const int tid  = threadIdx.x;
    const int lane = tid & 31;
    const int wp   = tid >> 5;             // warp id == pixel offset in block

    const int pix0 = blockIdx.x * 8;        // global pixel id of warp 0
    const int b    = pix0 / HWSZ;           // all 8 pixels share batch (HWSZ%8==0)
    const int hw0  = pix0 - b * HWSZ;

    // Cooperative left stage: 8 pixels x 256 channels. Consecutive tid reads
    // 8 consecutive w for one channel -> full 32B sectors.
    const float* lbase = left + (size_t)b * CC * HWSZ + hw0;
#pragma unroll
    for (int i = 0; i < 8; i++) {
        const int idx = tid + i * 256;       // 0..2047
        const int c = idx >> 3;
        const int p = idx & 7;
        s_left[p][c] = lbase[(size_t)c * HWSZ + p];
    }
    __syncthreads();

    // Lane l owns channels [8l, 8l+8)  ->  group g = l >> 3.
    float l[8];
    {
        const float4 t0 = *(const float4*)&s_left[wp][lane * 8];
        const float4 t1 = *(const float4*)&s_left[wp][lane * 8 + 4];
        l[0] = t0.x; l[1] = t0.y; l[2] = t0.z; l[3] = t0.w;
        l[4] = t1.x; l[5] = t1.y; l[6] = t1.z; l[7] = t1.w;
    }

    const int hw = hw0 + wp;
    const int h  = hw / WW;
    const int w  = hw - h * WW;

    const float fx = __ldg(flow + (size_t)(b * 2 + 0) * HWSZ + hw);
    const float fy = __ldg(flow + (size_t)(b * 2 + 1) * HWSZ + hw);
    const float cxb = (float)w + fx;
    const float cyb = (float)h + fy;

    const __half* rbase = g_rightT + (size_t)b * HWSZ * CC;
    const int g = lane >> 3;

#pragma unroll 1
    for (int k = 0; k < KK; k++) {
        const float ex = __ldg(extra + (size_t)(b * 2 * KK + 2 * k + 0) * HWSZ + hw);
        const float ey = __ldg(extra + (size_t)(b * 2 * KK + 2 * k + 1) * HWSZ + hw);

        const float cx = cxb + (float)(k - 4) + ex;
        const float cy = cyb + ey;

        const float x0f = floorf(cx);
        const float y0f = floorf(cy);
        const int x0 = (int)x0f;
        const int y0 = (int)y0f;
        const float ax = cx - x0f;
        const float ay = cy - y0f;

        float w00 = (1.0f - ax) * (1.0f - ay);
        float w01 = ax * (1.0f - ay);
        float w10 = (1.0f - ax) * ay;
        float w11 = ax * ay;

        const int x1 = x0 + 1, y1 = y0 + 1;
        const bool vx0 = (x0 >= 0) && (x0 <= WW - 1);
        const bool vx1 = (x1 >= 0) && (x1 <= WW - 1);
        const bool vy0 = (y0 >= 0) && (y0 <= HH - 1);
        const bool vy1 = (y1 >= 0) && (y1 <= HH - 1);
        if (!(vx0 && vy0)) w00 = 0.0f;
        if (!(vx1 && vy0)) w01 = 0.0f;
        if (!(vx0 && vy1)) w10 = 0.0f;
        if (!(vx1 && vy1)) w11 = 0.0f;

        const int ix0 = min(max(x0, 0), WW - 1);
        const int ix1 = min(max(x1, 0), WW - 1);
        const int iy0 = min(max(y0, 0), HH - 1);
        const int iy1 = min(max(y1, 0), HH - 1);

        // One LDG.128 per corner per lane (8 fp16 channels = 16 B).
        const uint4 va = *(const uint4*)(rbase + (size_t)(iy0 * WW + ix0) * CC + lane * 8);
        const uint4 vb = *(const uint4*)(rbase + (size_t)(iy0 * WW + ix1) * CC + lane * 8);
        const uint4 vc = *(const uint4*)(rbase + (size_t)(iy1 * WW + ix0) * CC + lane * 8);
        const uint4 vd = *(const uint4*)(rbase + (size_t)(iy1 * WW + ix1) * CC + lane * 8);

        const float d00 = dot8h(va, l);
        const float d01 = dot8h(vb, l);
        const float d10 = dot8h(vc, l);
        const float d11 = dot8h(vd, l);

        float s = w00 * d00 + w01 * d01 + w10 * d10 + w11 * d11;

        // Reduce over the 8 lanes of this group.
        s += __shfl_xor_sync(0xffffffffu, s, 1);
        s += __shfl_xor_sync(0xffffffffu, s, 2);
        s += __shfl_xor_sync(0xffffffffu, s, 4);

        if ((lane & 7) == 0) {
            // out[b, g*K + k, h, w]
            out[((size_t)(b * GROUPS + g) * KK + k) * HWSZ + hw] = s * (1.0f / 64.0f);
        }
    }
}

extern "C" void kernel_launch(void* const* d_in, const int* in_sizes, int n_in,
                              void* d_out, int out_size) {
    const float* left  = (const float*)d_in[0];
    const float* right = (const float*)d_in[1];
    const float* flow  = (const float*)d_in[2];
    const float* extra = (const float*)d_in[3];
    float* out = (float*)d_out;

    __half* rightT;
    cudaGetSymbolAddress((void**)&rightT, g_rightT);

    // Prepass: right NCHW fp32 -> NHWC fp16.
    dim3 tgrid(HWSZ / 32, CC / 32, BB);   // (576, 8, 2)
    dim3 tblk(32, 8, 1);
    transpose_convert_f16<<<tgrid, tblk>>>(right, rightT);

    // Main kernel: one warp per pixel; 8 warps (8 consecutive w) per block.
    const int blocks = (BB * HWSZ) / 8;   // 4608
    corr_kernel<<<blocks, 256>>>(left, flow, extra, out);
}